// round 4
// baseline (speedup 1.0000x reference)
#include <cuda_runtime.h>
#include <math.h>

// Fixed problem shape: B=4, L=4096, D=2048, G=16, gs=128
#define EPSV 1e-5f
#define VFLOOR 1e-6f

static constexpr int MAXBLG = 4 * 4096 * 16;   // B*L*G
__device__ float g_gm[MAXBLG];     // group means (B,L,G)
__device__ float g_mean[MAXBLG];   // running mean per (b,l,g)
__device__ float g_rstd[MAXBLG];   // rsqrt(var+eps) per (b,l,g)

// ---------------------------------------------------------------------------
// K1: group means. One block per (b,l) row; D/4 threads; warp w = group w
// (gs=128 floats = 32 lanes * float4). Coalesced float4 reads.
// ---------------------------------------------------------------------------
__global__ void k_groupmean(const float* __restrict__ x, int D, int G)
{
    const int row = blockIdx.x;                 // b*L + l
    const int gs  = D / G;                      // 128
    const int t   = threadIdx.x;                // 0..D/4-1
    const float4 v = reinterpret_cast<const float4*>(x + (size_t)row * D)[t];
    float s = (v.x + v.y) + (v.z + v.w);
    #pragma unroll
    for (int o = 16; o > 0; o >>= 1)
        s += __shfl_down_sync(0xffffffffu, s, o);
    if ((t & 31) == 0)
        g_gm[(size_t)row * G + (t >> 5)] = s / (float)gs;
}

// ---------------------------------------------------------------------------
// K2: per-(b,g) scan over L. 64 blocks, 512 threads, 8 elems/thread.
// Two chained inclusive block scans: (gm*valid, valid) then dd.
// ---------------------------------------------------------------------------
__global__ void k_scan(const int* __restrict__ prev_count,
                       const float* __restrict__ prev_mean,
                       const float* __restrict__ prev_var,
                       const int* __restrict__ pmask,   // bool stored as int32
                       float* __restrict__ outF,        // base of d_out (float)
                       int L, int G, int B,
                       int writeTail, long long tailOff)
{
    constexpr int P = 8;
    const int b = blockIdx.x / G;
    const int g = blockIdx.x - b * G;
    const int tid  = threadIdx.x;
    const int lane = tid & 31;
    const int wid  = tid >> 5;

    const float pc    = (float)prev_count[b];
    const float pmean = prev_mean[b * G + g];
    const float pvar  = prev_var[b * G + g];
    const float psum  = pmean * pc;
    const float pm2   = pvar * fmaxf(pc, 1.0f);

    __shared__ float smS[16], smC[16];

    // --- load + thread-local inclusive scan of (gm*valid, valid) ---
    float gv[P], vv[P], ls[P], lc[P];
    float sa = 0.f, ca = 0.f;
    #pragma unroll
    for (int j = 0; j < P; j++) {
        const int l = tid * P + j;
        const float gmv = g_gm[((size_t)b * L + l) * G + g];
        const float vd  = pmask[(size_t)b * L + l] ? 1.0f : 0.0f;
        gv[j] = gmv; vv[j] = vd;
        sa += gmv * vd;  ca += vd;
        ls[j] = sa;      lc[j] = ca;
    }

    // warp inclusive scan of thread totals
    float ws = sa, wc = ca;
    #pragma unroll
    for (int o = 1; o < 32; o <<= 1) {
        const float ns = __shfl_up_sync(0xffffffffu, ws, o);
        const float nc = __shfl_up_sync(0xffffffffu, wc, o);
        if (lane >= o) { ws += ns; wc += nc; }
    }
    const float exs = ws - sa, exc = wc - ca;   // exclusive within warp

    if (lane == 31) { smS[wid] = ws; smC[wid] = wc; }
    __syncthreads();
    if (tid == 0) {                    // exclusive scan of 16 warp totals
        float rs = 0.f, rc = 0.f;
        #pragma unroll
        for (int i = 0; i < 16; i++) {
            const float ts = smS[i], tc = smC[i];
            smS[i] = rs; smC[i] = rc;
            rs += ts; rc += tc;
        }
    }
    __syncthreads();
    const float baseS = smS[wid] + exs;
    const float baseC = smC[wid] + exc;

    // --- elementwise: mean_t, mean_{t-1}, dd ---
    float ddv[P], meanv[P], countv[P];
    #pragma unroll
    for (int j = 0; j < P; j++) {
        const float S = baseS + ls[j];
        const float C = baseC + lc[j];
        const float count_t = pc + C;
        const float sum_t   = psum + S;
        const float mean_t  = (count_t > 0.f) ? sum_t / fmaxf(count_t, 1.f) : pmean;
        const float exS2 = S - gv[j] * vv[j];
        const float exC2 = C - vv[j];
        const float cp = pc + exC2;
        const float mean_p = (cp > 0.f) ? (psum + exS2) / fmaxf(cp, 1.f) : pmean;
        ddv[j]   = (gv[j] - mean_p) * (gv[j] - mean_t) * vv[j];
        meanv[j] = mean_t;
        countv[j] = count_t;
    }
    __syncthreads();   // smS/smC reads above done before reuse

    // --- second scan: dd ---
    float ld[P];
    float da = 0.f;
    #pragma unroll
    for (int j = 0; j < P; j++) { da += ddv[j]; ld[j] = da; }
    float wd = da;
    #pragma unroll
    for (int o = 1; o < 32; o <<= 1) {
        const float nd = __shfl_up_sync(0xffffffffu, wd, o);
        if (lane >= o) wd += nd;
    }
    const float exd = wd - da;
    if (lane == 31) smS[wid] = wd;
    __syncthreads();
    if (tid == 0) {
        float rd = 0.f;
        #pragma unroll
        for (int i = 0; i < 16; i++) { const float td = smS[i]; smS[i] = rd; rd += td; }
    }
    __syncthreads();
    const float baseD = smS[wid] + exd;

    #pragma unroll
    for (int j = 0; j < P; j++) {
        const int l = tid * P + j;
        const float Dv = baseD + ld[j];
        const float m2 = pm2 + Dv;
        float var = (countv[j] > 0.f) ? m2 / fmaxf(countv[j], 1.f) : pvar;
        var = fmaxf(var, VFLOOR);
        const size_t idx = ((size_t)b * L + l) * G + g;
        g_mean[idx] = meanv[j];
        g_rstd[idx] = rsqrtf(var + EPSV);
        if (writeTail && l == L - 1) {
            // layout: [y | new_count (B) | mean_last (B*G) | var_last (B*G)]
            outF[tailOff + B + (size_t)b * G + g]           = meanv[j];
            outF[tailOff + B + (size_t)B * G + (size_t)b * G + g] = var;
            if (g == 0) {
                const float C = baseC + lc[j];
                outF[tailOff + b] = pc + C;   // new_count as float
            }
        }
    }
}

// ---------------------------------------------------------------------------
// K3: normalize + affine, float4 elementwise.
// ---------------------------------------------------------------------------
__global__ void k_norm(const float* __restrict__ x,
                       const float* __restrict__ weight,
                       const float* __restrict__ bias,
                       float* __restrict__ y,
                       int D4, int G, int gs, long long n4)
{
    const long long i = (long long)blockIdx.x * blockDim.x + threadIdx.x;
    if (i >= n4) return;
    const int d4 = (int)(i % D4);
    const long long row = i / D4;
    const int g = (d4 * 4) / gs;
    const float mean = g_mean[row * G + g];
    const float rstd = g_rstd[row * G + g];
    const float4 xv = reinterpret_cast<const float4*>(x)[i];
    const float4 wv = reinterpret_cast<const float4*>(weight)[d4];
    const float4 bv = reinterpret_cast<const float4*>(bias)[d4];
    float4 o;
    o.x = (xv.x - mean) * rstd * (wv.x + 1.f) + bv.x;
    o.y = (xv.y - mean) * rstd * (wv.y + 1.f) + bv.y;
    o.z = (xv.z - mean) * rstd * (wv.z + 1.f) + bv.z;
    o.w = (xv.w - mean) * rstd * (wv.w + 1.f) + bv.w;
    reinterpret_cast<float4*>(y)[i] = o;
}

// ---------------------------------------------------------------------------
extern "C" void kernel_launch(void* const* d_in, const int* in_sizes, int n_in,
                              void* d_out, int out_size)
{
    const float* x     = (const float*)d_in[0];
    const int*   pcnt  = (const int*)d_in[1];
    const float* pmean = (const float*)d_in[2];
    const float* pvar  = (const float*)d_in[3];
    const int*   pmask = (const int*)d_in[4];    // bool as int32
    const float* wgt   = (const float*)d_in[5];
    const float* bias  = (const float*)d_in[6];
    float*       outF  = (float*)d_out;

    const int B = in_sizes[1];
    const int G = in_sizes[2] / B;
    const int D = in_sizes[5];
    const int L = in_sizes[4] / B;
    const int gs = D / G;
    const long long BLD = (long long)B * L * D;
    const long long expected = BLD + B + 2LL * B * G;
    const int writeTail = (out_size >= expected) ? 1 : 0;

    // K1: group means
    k_groupmean<<<B * L, D / 4>>>(x, D, G);

    // K2: scan (requires L == 512*8)
    k_scan<<<B * G, 512>>>(pcnt, pmean, pvar, pmask, outF, L, G, B, writeTail, BLD);

    // K3: normalize
    const long long n4 = BLD / 4;
    const int threads = 256;
    const long long blocks = (n4 + threads - 1) / threads;
    k_norm<<<(unsigned)blocks, threads>>>(x, wgt, bias, outF, D / 4, G, gs, n4);
}